// round 1
// baseline (speedup 1.0000x reference)
#include <cuda_runtime.h>

#define Bc 256
#define Tc 512
#define Cc 256
#define Lc 64
#define Sc 129            // 2*L+1
#define GS 65             // gathered classes per (b,t): blank + L labels
#define NEGF (-1e30f)

// scratch (static device arrays; no allocation allowed)
__device__ float g_gath[(size_t)Bc * Tc * GS];   // ~34 MB, L2-resident
__device__ float g_loss[Bc];

// ---------------------------------------------------------------------------
// Kernel A: per (b,t) row — log-softmax normalizer + gather of label classes.
// gath[b,t,j] = logits[b,t,cls_j] - logsumexp_c(logits[b,t,:])
//   cls_0 = blank(0), cls_j = targets[b, j-1] for j=1..L
// ---------------------------------------------------------------------------
__global__ __launch_bounds__(Cc) void lse_gather_kernel(
    const float* __restrict__ logits, const int* __restrict__ targets)
{
    const int row = blockIdx.x;           // b*T + t
    const int tid = threadIdx.x;          // class index
    const int b   = row / Tc;

    __shared__ float sh[Cc];
    __shared__ float redm[8];
    __shared__ float reds[8];

    const float x = logits[(size_t)row * Cc + tid];
    sh[tid] = x;

    // block max
    float m = x;
    #pragma unroll
    for (int o = 16; o; o >>= 1) m = fmaxf(m, __shfl_xor_sync(0xffffffffu, m, o));
    if ((tid & 31) == 0) redm[tid >> 5] = m;
    __syncthreads();
    float rm = redm[0];
    #pragma unroll
    for (int i = 1; i < 8; i++) rm = fmaxf(rm, redm[i]);

    // block sum of exp(x - max)
    float e = __expf(x - rm);
    #pragma unroll
    for (int o = 16; o; o >>= 1) e += __shfl_xor_sync(0xffffffffu, e, o);
    if ((tid & 31) == 0) reds[tid >> 5] = e;
    __syncthreads();
    float sum = reds[0];
    #pragma unroll
    for (int i = 1; i < 8; i++) sum += reds[i];

    const float lse = rm + __logf(sum);

    if (tid < GS) {
        const int cls = (tid == 0) ? 0 : targets[b * Lc + tid - 1];
        g_gath[(size_t)row * GS + tid] = sh[cls] - lse;
    }
}

// ---------------------------------------------------------------------------
// Kernel B: per-batch forward recursion over T. One thread per extended state.
// Double-buffered alpha in SMEM (padded by 2 for s-1 / s-2 shifts),
// one barrier per timestep, next-step log-probs prefetched across the barrier.
// ---------------------------------------------------------------------------
__global__ __launch_bounds__(160) void alpha_kernel(
    const int* __restrict__ targets,
    const int* __restrict__ in_len,
    const int* __restrict__ tgt_len)
{
    const int b = blockIdx.x;
    const int s = threadIdx.x;
    const bool active = (s < Sc);

    __shared__ float A[2][Sc + 2];        // state s lives at index s+2
    if (threadIdx.x < 2) { A[0][threadIdx.x] = NEGF; A[1][threadIdx.x] = NEGF; }

    // gathered-class index for this state: even s -> blank(0), odd s=2k+1 -> k+1
    const int j = (s & 1) ? ((s + 1) >> 1) : 0;

    // skip transition s-2 -> s allowed iff ext[s]!=blank && ext[s]!=ext[s-2]
    bool skip = false;
    if (active && (s & 1) && s >= 3) {
        const int k = (s - 1) >> 1;
        skip = (targets[b * Lc + k] != targets[b * Lc + k - 1]);
    }

    const int tlen = in_len[b];
    const float* __restrict__ gb = g_gath + (size_t)b * Tc * GS;

    if (active) A[0][s + 2] = (s < 2) ? gb[j] : NEGF;   // alpha at t=0

    float lp_next = active ? gb[GS + j] : 0.f;          // prefetch t=1
    #pragma unroll 1
    for (int t = 1; t < Tc; ++t) {
        const float lp = lp_next;
        if (active && t + 1 < Tc) lp_next = gb[(size_t)(t + 1) * GS + j];
        const int cur = t & 1, prev = cur ^ 1;
        __syncthreads();                 // orders prev-buffer writes vs reads
        if (active) {
            const float a1 = A[prev][s + 2];
            const float a2 = A[prev][s + 1];
            const float a3 = skip ? A[prev][s] : NEGF;
            float m = fmaxf(a1, fmaxf(a2, a3));
            float v = m + __logf(__expf(a1 - m) + __expf(a2 - m) + __expf(a3 - m)) + lp;
            v = fmaxf(v, NEGF);
            // freeze rows whose input sequence already ended
            A[cur][s + 2] = (t < tlen) ? v : a1;
        }
    }
    __syncthreads();

    if (threadIdx.x == 0) {
        const int last = (Tc - 1) & 1;
        const int tl = tgt_len[b];
        const float al = A[last][2 * tl + 2];      // alpha[2*tl]
        const float ap = A[last][2 * tl + 1];      // alpha[2*tl - 1]
        const float m = fmaxf(al, ap);
        float loss = -(m + log1pf(__expf(fminf(al, ap) - m)));
        if (loss > 1e20f) loss = 0.f;              // zero_infinity
        g_loss[b] = loss / (float)tl;
    }
}

// ---------------------------------------------------------------------------
// Kernel C: deterministic mean over batch.
// ---------------------------------------------------------------------------
__global__ __launch_bounds__(Bc) void reduce_kernel(float* __restrict__ out)
{
    const int tid = threadIdx.x;
    float v = g_loss[tid];
    #pragma unroll
    for (int o = 16; o; o >>= 1) v += __shfl_xor_sync(0xffffffffu, v, o);
    __shared__ float r[8];
    if ((tid & 31) == 0) r[tid >> 5] = v;
    __syncthreads();
    if (tid == 0) {
        float ssum = 0.f;
        #pragma unroll
        for (int i = 0; i < 8; i++) ssum += r[i];
        out[0] = ssum / (float)Bc;
    }
}

extern "C" void kernel_launch(void* const* d_in, const int* in_sizes, int n_in,
                              void* d_out, int out_size)
{
    const float* logits  = (const float*)d_in[0];   // [B,T,C] f32
    const int*   targets = (const int*)d_in[1];     // [B,L] i32
    const int*   in_len  = (const int*)d_in[2];     // [B] i32
    const int*   tgt_len = (const int*)d_in[3];     // [B] i32
    (void)in_sizes; (void)n_in; (void)out_size;

    lse_gather_kernel<<<Bc * Tc, Cc>>>(logits, targets);
    alpha_kernel<<<Bc, 160>>>(targets, in_len, tgt_len);
    reduce_kernel<<<1, Bc>>>((float*)d_out);
}

// round 4
// speedup vs baseline: 4.1959x; 4.1959x over previous
#include <cuda_runtime.h>
#include <cstdint>

#define Bc 256
#define Tc 512
#define Cc 256
#define Lc 64
#define Sc 129            // 2*L+1
#define GSP 68            // padded gathered row (65 used, 16B-aligned stride)
#define LOG2E 1.4426950408889634f
#define LN2 0.6931471805599453f
#define NEGF (-1e30f)

// scratch (static device arrays; no allocation allowed)
__device__ float g_gath[(size_t)Bc * Tc * GSP];   // log2 probs, ~35.6 MB
__device__ float g_loss[Bc];

// ---------------------------------------------------------------------------
// Kernel A: warp-per-row log-softmax + gather of the 65 label classes,
// stored as LOG2 probabilities. No SMEM, no block barriers.
// ---------------------------------------------------------------------------
__global__ __launch_bounds__(256) void lse_gather_kernel(
    const float* __restrict__ logits, const int* __restrict__ targets)
{
    const int w    = threadIdx.x >> 5;
    const int lane = threadIdx.x & 31;
    const int row  = blockIdx.x * 8 + w;        // b*T + t
    const int b    = row >> 9;                  // T = 512

    const float* __restrict__ rf = logits + (size_t)row * Cc;
    const float4* rp = (const float4*)rf;
    const float4 v0 = rp[lane];
    const float4 v1 = rp[lane + 32];

    // warp max
    float m = fmaxf(fmaxf(fmaxf(v0.x, v0.y), fmaxf(v0.z, v0.w)),
                    fmaxf(fmaxf(v1.x, v1.y), fmaxf(v1.z, v1.w)));
    #pragma unroll
    for (int o = 16; o; o >>= 1) m = fmaxf(m, __shfl_xor_sync(0xffffffffu, m, o));

    // warp sum of exp
    float s = exp2f((v0.x - m) * LOG2E) + exp2f((v0.y - m) * LOG2E)
            + exp2f((v0.z - m) * LOG2E) + exp2f((v0.w - m) * LOG2E)
            + exp2f((v1.x - m) * LOG2E) + exp2f((v1.y - m) * LOG2E)
            + exp2f((v1.z - m) * LOG2E) + exp2f((v1.w - m) * LOG2E);
    #pragma unroll
    for (int o = 16; o; o >>= 1) s += __shfl_xor_sync(0xffffffffu, s, o);

    const float l2s = __log2f(s);

    const int* __restrict__ tg = targets + b * Lc;
    float* __restrict__ out = g_gath + (size_t)row * GSP;
    #pragma unroll
    for (int j = lane; j < 65; j += 32) {
        const int cls = j ? tg[j - 1] : 0;
        out[j] = (rf[cls] - m) * LOG2E - l2s;   // log2 prob (L1 hit)
    }
}

// ---------------------------------------------------------------------------
// log-add-exp in base 2
// ---------------------------------------------------------------------------
__device__ __forceinline__ float lae2(float x, float y) {
    const float mx = fmaxf(x, y);
    const float mn = fminf(x, y);
    return mx + __log2f(1.0f + exp2f(mn - mx));
}
__device__ __forceinline__ float lae3(float x, float y, float z) {
    const float mx = fmaxf(x, fmaxf(y, z));
    return mx + __log2f(exp2f(x - mx) + exp2f(y - mx) + exp2f(z - mx));
}

// ---------------------------------------------------------------------------
// Kernel B: one warp per batch row. Alpha recursion in LOG2 domain,
// register-resident states (4 per lane + state 128), one shfl_up per step,
// cp.async double-buffered staging, early stop at input_length.
// ---------------------------------------------------------------------------
__device__ __forceinline__ void cpa16(uint32_t dst_smem, const void* src) {
    asm volatile("cp.async.cg.shared.global [%0], [%1], 16;\n"
                 :: "r"(dst_smem), "l"(src));
}
__device__ __forceinline__ void cpa_commit() {
    asm volatile("cp.async.commit_group;\n" ::: "memory");
}
__device__ __forceinline__ void cpa_wait1() {
    asm volatile("cp.async.wait_group 1;\n" ::: "memory");
}
__device__ __forceinline__ void cpa_wait0() {
    asm volatile("cp.async.wait_group 0;\n" ::: "memory");
}

#define CHUNK 64
#define NCHUNK (Tc / CHUNK)          // 8
#define CHUNK_V16 (CHUNK * GSP / 4)  // 1088 16-byte vectors per chunk

__global__ __launch_bounds__(32) void alpha_kernel(
    const int* __restrict__ targets,
    const int* __restrict__ in_len,
    const int* __restrict__ tgt_len)
{
    const int b    = blockIdx.x;
    const int lane = threadIdx.x;

    __shared__ float stg[2][CHUNK * GSP];   // 34816 B double buffer
    __shared__ float fin[132];

    const float* __restrict__ gb = g_gath + (size_t)b * Tc * GSP;
    const int*   __restrict__ tg = targets + b * Lc;
    const int tlen = in_len[b];

    // per-lane constants: lane l holds extended states 4l..4l+3 (a0..a3),
    // lane 31 additionally owns state 128 (a4).
    const int j1 = 2 * lane + 1;     // gathered index for state 4l+1
    const int j3 = 2 * lane + 2;     // gathered index for state 4l+3
    bool sk1 = false, sk3;
    if (lane > 0) sk1 = (tg[2 * lane] != tg[2 * lane - 1]);
    sk3 = (tg[2 * lane + 1] != tg[2 * lane]);

    // stage chunks 0 and 1
    {
        const uint32_t s0 = (uint32_t)__cvta_generic_to_shared(&stg[0][0]);
        const uint32_t s1 = (uint32_t)__cvta_generic_to_shared(&stg[1][0]);
        const char* g0 = (const char*)gb;
        const char* g1 = (const char*)(gb + CHUNK * GSP);
        for (int i = lane; i < CHUNK_V16; i += 32) cpa16(s0 + i * 16, g0 + i * 16);
        cpa_commit();
        for (int i = lane; i < CHUNK_V16; i += 32) cpa16(s1 + i * 16, g1 + i * 16);
        cpa_commit();
        cpa_wait1();          // chunk 0 ready
        __syncwarp();
    }

    // alpha at t=0 (log2 domain): state0 = lp_blank(0), state1 = lp_label0(0)
    float a0 = (lane == 0) ? stg[0][0] : NEGF;
    float a1 = (lane == 0) ? stg[0][1] : NEGF;
    float a2 = NEGF, a3 = NEGF, a4 = NEGF;

    int t = 1;
    #pragma unroll 1
    for (int c = 0; c < NCHUNK; ++c) {
        const float* __restrict__ sp = stg[c & 1];
        const int tcend = ((c + 1) * CHUNK < tlen) ? (c + 1) * CHUNK : tlen;

        #pragma unroll 1
        for (; t < tcend; ++t) {
            const float* q = sp + (t - c * CHUNK) * GSP;
            const float lpb = q[0];
            const float lpA = q[j1];
            const float lpB = q[j3];
            float p = __shfl_up_sync(0xffffffffu, a3, 1);   // alpha[4l-1]
            if (lane == 0) p = NEGF;
            const float n0 = fmaxf(lae2(a0, p) + lpb, NEGF);
            const float n1 = fmaxf(lae3(a0, a1, sk1 ? p : NEGF) + lpA, NEGF);
            const float n2 = fmaxf(lae2(a1, a2) + lpb, NEGF);
            const float n3 = fmaxf(lae3(a2, a3, sk3 ? a1 : NEGF) + lpB, NEGF);
            a4 = fmaxf(lae2(a3, a4) + lpb, NEGF);           // state 128 (lane 31)
            a0 = n0; a1 = n1; a2 = n2; a3 = n3;
        }
        if (tcend == tlen) break;             // recursion frozen beyond tlen

        // prefetch chunk c+2 into the buffer we just finished reading
        __syncwarp();
        if (c + 2 < NCHUNK && (c + 2) * CHUNK < tlen) {
            const uint32_t d = (uint32_t)__cvta_generic_to_shared(&stg[c & 1][0]);
            const char* g = (const char*)(gb + (size_t)(c + 2) * CHUNK * GSP);
            for (int i = lane; i < CHUNK_V16; i += 32) cpa16(d + i * 16, g + i * 16);
        }
        cpa_commit();
        cpa_wait1();          // chunk c+1 ready
        __syncwarp();
    }

    cpa_wait0();              // drain in-flight copies before SMEM reuse/exit
    __syncwarp();

    // publish states, compute loss on lane 0
    fin[4 * lane + 0] = a0;
    fin[4 * lane + 1] = a1;
    fin[4 * lane + 2] = a2;
    fin[4 * lane + 3] = a3;
    if (lane == 31) fin[128] = a4;
    __syncwarp();

    if (lane == 0) {
        const int tl = tgt_len[b];
        const float v = lae2(fin[2 * tl], fin[2 * tl - 1]);   // log2 total prob
        float loss = -LN2 * v;
        if (!(loss < 1e20f)) loss = 0.f;       // zero_infinity (also NaN guard)
        g_loss[b] = loss / (float)tl;
    }
}

// ---------------------------------------------------------------------------
// Kernel C: deterministic mean over batch.
// ---------------------------------------------------------------------------
__global__ __launch_bounds__(Bc) void reduce_kernel(float* __restrict__ out)
{
    const int tid = threadIdx.x;
    float v = g_loss[tid];
    #pragma unroll
    for (int o = 16; o; o >>= 1) v += __shfl_xor_sync(0xffffffffu, v, o);
    __shared__ float r[8];
    if ((tid & 31) == 0) r[tid >> 5] = v;
    __syncthreads();
    if (tid == 0) {
        float ssum = 0.f;
        #pragma unroll
        for (int i = 0; i < 8; i++) ssum += r[i];
        out[0] = ssum / (float)Bc;
    }
}

extern "C" void kernel_launch(void* const* d_in, const int* in_sizes, int n_in,
                              void* d_out, int out_size)
{
    const float* logits  = (const float*)d_in[0];   // [B,T,C] f32
    const int*   targets = (const int*)d_in[1];     // [B,L] i32
    const int*   in_len  = (const int*)d_in[2];     // [B] i32
    const int*   tgt_len = (const int*)d_in[3];     // [B] i32
    (void)in_sizes; (void)n_in; (void)out_size;

    lse_gather_kernel<<<(Bc * Tc) / 8, 256>>>(logits, targets);
    alpha_kernel<<<Bc, 32>>>(targets, in_len, tgt_len);
    reduce_kernel<<<1, Bc>>>((float*)d_out);
}

// round 5
// speedup vs baseline: 5.1305x; 1.2227x over previous
#include <cuda_runtime.h>
#include <cstdint>

#define Bc 256
#define Tc 512
#define Cc 256
#define Lc 64
#define Sc 129            // 2*L+1
#define GSP 68            // padded gathered row (65 used, 16B-aligned stride)
#define LOG2E 1.4426950408889634f
#define LN2 0.6931471805599453f
#define SENT (-(1 << 20))  // exponent sentinel for unreached lanes

// scratch (static device arrays; no allocation allowed)
__device__ float g_gath[(size_t)Bc * Tc * GSP];   // LINEAR probs, ~35.6 MB
__device__ float g_loss[Bc];

// ---------------------------------------------------------------------------
// Kernel A: warp-per-row softmax + gather of the 65 label classes, stored as
// LINEAR probabilities. Rows with t >= input_length are skipped entirely.
// ---------------------------------------------------------------------------
__global__ __launch_bounds__(256) void lse_gather_kernel(
    const float* __restrict__ logits, const int* __restrict__ targets,
    const int* __restrict__ in_len)
{
    const int w    = threadIdx.x >> 5;
    const int lane = threadIdx.x & 31;
    const int row  = blockIdx.x * 8 + w;        // b*T + t
    const int b    = row >> 9;                  // T = 512
    const int t    = row & 511;

    if (t >= __ldg(&in_len[b])) return;         // never read by alpha

    const float* __restrict__ rf = logits + (size_t)row * Cc;
    const float4* rp = (const float4*)rf;
    const float4 v0 = rp[lane];
    const float4 v1 = rp[lane + 32];

    // warp max
    float m = fmaxf(fmaxf(fmaxf(v0.x, v0.y), fmaxf(v0.z, v0.w)),
                    fmaxf(fmaxf(v1.x, v1.y), fmaxf(v1.z, v1.w)));
    #pragma unroll
    for (int o = 16; o; o >>= 1) m = fmaxf(m, __shfl_xor_sync(0xffffffffu, m, o));

    // warp sum of exp
    float s = exp2f((v0.x - m) * LOG2E) + exp2f((v0.y - m) * LOG2E)
            + exp2f((v0.z - m) * LOG2E) + exp2f((v0.w - m) * LOG2E)
            + exp2f((v1.x - m) * LOG2E) + exp2f((v1.y - m) * LOG2E)
            + exp2f((v1.z - m) * LOG2E) + exp2f((v1.w - m) * LOG2E);
    #pragma unroll
    for (int o = 16; o; o >>= 1) s += __shfl_xor_sync(0xffffffffu, s, o);

    const float l2s = __log2f(s);

    const int* __restrict__ tg = targets + b * Lc;
    float* __restrict__ out = g_gath + (size_t)row * GSP;
    #pragma unroll
    for (int j = lane; j < 65; j += 32) {
        const int cls = j ? tg[j - 1] : 0;
        out[j] = exp2f((rf[cls] - m) * LOG2E - l2s);   // linear prob (L1 hit)
    }
}

// ---------------------------------------------------------------------------
// Kernel B: one warp per batch row. Alpha recursion in LINEAR domain with
// per-lane power-of-2 scaling (mantissa + int exponent, renormalized every
// step via exact exponent-bit tricks — zero MUFU in the loop).
// Lane l owns states 4l..4l+3; lane 31 additionally owns state 128.
// ---------------------------------------------------------------------------
__device__ __forceinline__ void cpa16(uint32_t dst_smem, const void* src) {
    asm volatile("cp.async.cg.shared.global [%0], [%1], 16;\n"
                 :: "r"(dst_smem), "l"(src));
}
__device__ __forceinline__ void cpa_commit() {
    asm volatile("cp.async.commit_group;\n" ::: "memory");
}
__device__ __forceinline__ void cpa_wait1() {
    asm volatile("cp.async.wait_group 1;\n" ::: "memory");
}
__device__ __forceinline__ void cpa_wait0() {
    asm volatile("cp.async.wait_group 0;\n" ::: "memory");
}

#define CHUNK 64
#define NCHUNK (Tc / CHUNK)          // 8
#define CHUNK_V16 (CHUNK * GSP / 4)  // 1088 16-byte vectors per chunk

__global__ __launch_bounds__(32) void alpha_kernel(
    const int* __restrict__ targets,
    const int* __restrict__ in_len,
    const int* __restrict__ tgt_len)
{
    const int b    = blockIdx.x;
    const int lane = threadIdx.x;

    __shared__ float stg[2][CHUNK * GSP];   // 34816 B double buffer
    __shared__ float fin_m[132];
    __shared__ int   fin_e[33];

    const float* __restrict__ gb = g_gath + (size_t)b * Tc * GSP;
    const int*   __restrict__ tg = targets + b * Lc;
    const int tlen = in_len[b];

    // per-lane constants
    const int j1 = 2 * lane + 1;     // gathered index for state 4l+1
    const int j3 = 2 * lane + 2;     // gathered index for state 4l+3
    float sk1f = 0.f, sk3f;
    if (lane > 0) sk1f = (tg[2 * lane] != tg[2 * lane - 1]) ? 1.f : 0.f;
    sk3f = (tg[2 * lane + 1] != tg[2 * lane]) ? 1.f : 0.f;

    // stage chunks 0 and 1
    {
        const uint32_t s0 = (uint32_t)__cvta_generic_to_shared(&stg[0][0]);
        const uint32_t s1 = (uint32_t)__cvta_generic_to_shared(&stg[1][0]);
        const char* g0 = (const char*)gb;
        const char* g1 = (const char*)(gb + CHUNK * GSP);
        for (int i = lane; i < CHUNK_V16; i += 32) cpa16(s0 + i * 16, g0 + i * 16);
        cpa_commit();
        for (int i = lane; i < CHUNK_V16; i += 32) cpa16(s1 + i * 16, g1 + i * 16);
        cpa_commit();
        cpa_wait1();          // chunk 0 ready
        __syncwarp();
    }

    // t=0: state0 = p_blank(0), state1 = p_label0(0) (lane 0, scale 2^0)
    float a0 = (lane == 0) ? stg[0][0] : 0.f;
    float a1 = (lane == 0) ? stg[0][1] : 0.f;
    float a2 = 0.f, a3 = 0.f, a4 = 0.f;
    int   E  = (lane == 0) ? 0 : SENT;

    int t = 1;
    #pragma unroll 1
    for (int c = 0; c < NCHUNK; ++c) {
        const float* __restrict__ sp = stg[c & 1];
        const int tcend = ((c + 1) * CHUNK < tlen) ? (c + 1) * CHUNK : tlen;
        const float* q = sp + (t - c * CHUNK) * GSP;

        #pragma unroll 2
        for (; t < tcend; ++t, q += GSP) {
            const float lpb = q[0];
            const float lpA = q[j1];
            const float lpB = q[j3];

            float pm = __shfl_up_sync(0xffffffffu, a3, 1);  // alpha[4l-1] mant
            int   pe = __shfl_up_sync(0xffffffffu, E,  1);  // its scale
            if (lane == 0) { pm = 0.f; pe = SENT; }

            // unify scales (factors are exact powers of two <= 1)
            const int eu = max(E, pe);
            const int dl = max(E  - eu, -127);
            const int dp = max(pe - eu, -127);
            const float sl  = __int_as_float((dl + 127) << 23);
            const float spf = __int_as_float((dp + 127) << 23);
            const float p = pm * spf;
            a0 *= sl; a1 *= sl; a2 *= sl; a3 *= sl; a4 *= sl;

            const float n0 = (a0 + p) * lpb;
            const float n1 = fmaf(sk1f, p,  a0 + a1) * lpA;
            const float n2 = (a1 + a2) * lpb;
            const float n3 = fmaf(sk3f, a1, a2 + a3) * lpB;
            a4 = (a3 + a4) * lpb;                    // state 128 (lane 31)

            // exact per-lane renormalization (no MUFU)
            const float m4 = (lane == 31) ? a4 : 0.f;
            const float mx = fmaxf(fmaxf(n0, n1), fmaxf(fmaxf(n2, n3), m4));
            if (mx > 0.f) {
                const int k = (__float_as_int(mx) >> 23) - 127;   // floor(log2 mx)
                const float sc = __int_as_float((127 - k) << 23); // 2^-k (exact)
                a0 = n0 * sc; a1 = n1 * sc; a2 = n2 * sc; a3 = n3 * sc; a4 *= sc;
                E = eu + k;
            } else {
                a0 = a1 = a2 = a3 = 0.f;
                E = SENT;                            // lane (still) unreached
            }
        }
        if (tcend == tlen) break;             // recursion frozen beyond tlen

        // prefetch chunk c+2 into the buffer we just finished reading
        __syncwarp();
        if (c + 2 < NCHUNK && (c + 2) * CHUNK < tlen) {
            const uint32_t d = (uint32_t)__cvta_generic_to_shared(&stg[c & 1][0]);
            const char* g = (const char*)(gb + (size_t)(c + 2) * CHUNK * GSP);
            for (int i = lane; i < CHUNK_V16; i += 32) cpa16(d + i * 16, g + i * 16);
        }
        cpa_commit();
        cpa_wait1();          // chunk c+1 ready
        __syncwarp();
    }

    cpa_wait0();              // drain in-flight copies before exit
    __syncwarp();

    // publish states (mantissa + per-lane exponent), compute loss on lane 0
    fin_m[4 * lane + 0] = a0;
    fin_m[4 * lane + 1] = a1;
    fin_m[4 * lane + 2] = a2;
    fin_m[4 * lane + 3] = a3;
    fin_e[lane] = E;
    if (lane == 31) { fin_m[128] = a4; fin_e[32] = E; }
    __syncwarp();

    if (lane == 0) {
        const int tl = tgt_len[b];
        const int s1 = 2 * tl, s2 = 2 * tl - 1;
        const float m1 = fin_m[s1];  const int e1 = fin_e[s1 >> 2];
        const float m2 = fin_m[s2];  const int e2 = fin_e[s2 >> 2];
        const int eu = max(e1, e2);
        const float f1 = __int_as_float((max(e1 - eu, -127) + 127) << 23);
        const float f2 = __int_as_float((max(e2 - eu, -127) + 127) << 23);
        const float sum = m1 * f1 + m2 * f2;
        float loss = 0.f;
        if (sum > 0.f) {
            loss = -LN2 * (__log2f(sum) + (float)eu);
            if (!(loss < 1e20f)) loss = 0.f;   // zero_infinity (also NaN guard)
        }
        g_loss[b] = loss / (float)tl;
    }
}

// ---------------------------------------------------------------------------
// Kernel C: deterministic mean over batch.
// ---------------------------------------------------------------------------
__global__ __launch_bounds__(Bc) void reduce_kernel(float* __restrict__ out)
{
    const int tid = threadIdx.x;
    float v = g_loss[tid];
    #pragma unroll
    for (int o = 16; o; o >>= 1) v += __shfl_xor_sync(0xffffffffu, v, o);
    __shared__ float r[8];
    if ((tid & 31) == 0) r[tid >> 5] = v;
    __syncthreads();
    if (tid == 0) {
        float ssum = 0.f;
        #pragma unroll
        for (int i = 0; i < 8; i++) ssum += r[i];
        out[0] = ssum / (float)Bc;
    }
}

extern "C" void kernel_launch(void* const* d_in, const int* in_sizes, int n_in,
                              void* d_out, int out_size)
{
    const float* logits  = (const float*)d_in[0];   // [B,T,C] f32
    const int*   targets = (const int*)d_in[1];     // [B,L] i32
    const int*   in_len  = (const int*)d_in[2];     // [B] i32
    const int*   tgt_len = (const int*)d_in[3];     // [B] i32
    (void)in_sizes; (void)n_in; (void)out_size;

    lse_gather_kernel<<<(Bc * Tc) / 8, 256>>>(logits, targets, in_len);
    alpha_kernel<<<Bc, 32>>>(targets, in_len, tgt_len);
    reduce_kernel<<<1, Bc>>>((float*)d_out);
}